// round 4
// baseline (speedup 1.0000x reference)
#include <cuda_runtime.h>
#include <cuda_bf16.h>
#include <cstdint>

// ChamferDistance via sorted-z pruned exact NN search.
// Per (set,batch): sort points by z. For each (sorted) query, scan refs
// outward from its z-rank; sound early exit when frontier z-gap^2 >= best.
// d(q,r) = q2 + dot4((qx,qy,qz,1), (-2rx,-2ry,-2rz,||r||^2)).

#define BATCH    16
#define NPTS     4096
#define PAD      256
#define SLEN     (NPTS + 2 * PAD)      // 4608 entries per sorted array
#define WIN      512                   // initial window refs per query
#define WROUNDS  (WIN / 32)            // 16
#define STHREADS 512
#define THREADS  256
#define NWARP    (THREADS / 32)        // 8
#define CHUNKS   32                    // query chunks per (dir,b)
#define QPB      (NPTS / CHUNKS)       // 128 queries per block
#define QPW      (QPB / NWARP)         // 16 queries per warp
#define NBLK     (CHUNKS * BATCH * 2)  // 1024 search blocks

// sorted entry i: (-2x, -2y, -2z, x^2+y^2+z^2); pads give huge distance and
// never satisfy "rz < qz" (s.z = -1e30 => rz = +5e29).
__device__ float4 g_sorted[2 * BATCH][SLEN];
__device__ float  g_bsum[NBLK];

__device__ __forceinline__ unsigned ordkey(float f) {
    unsigned u = __float_as_uint(f);
    return (u & 0x80000000u) ? ~u : (u | 0x80000000u);
}

// ---------------- sort: bitonic on (z-key | index), then gather+transform ----
__global__ __launch_bounds__(STHREADS)
void chamfer_sort_kernel(const float* __restrict__ x, const float* __restrict__ y) {
    __shared__ unsigned long long keys[NPTS];
    const int b = blockIdx.x, set = blockIdx.y;
    const float* src = (set == 0 ? x : y) + (size_t)b * NPTS * 3;
    const int tid = threadIdx.x;

    for (int i = tid; i < NPTS; i += STHREADS) {
        float z = src[i * 3 + 2];
        keys[i] = ((unsigned long long)ordkey(z) << 32) | (unsigned)i;
    }
    for (int k = 2; k <= NPTS; k <<= 1) {
        for (int j = k >> 1; j > 0; j >>= 1) {
            __syncthreads();
            for (int i = tid; i < NPTS; i += STHREADS) {
                int l = i ^ j;
                if (l > i) {
                    unsigned long long a = keys[i], c = keys[l];
                    bool asc = ((i & k) == 0);
                    if ((a > c) == asc) { keys[i] = c; keys[l] = a; }
                }
            }
        }
    }
    __syncthreads();

    float4* out = g_sorted[set * BATCH + b];
    const float4 padv = make_float4(0.f, 0.f, -1e30f, 1e37f);
    for (int i = tid; i < PAD; i += STHREADS) {
        out[i] = padv;
        out[PAD + NPTS + i] = padv;
    }
    for (int i = tid; i < NPTS; i += STHREADS) {
        int idx = (int)(unsigned)keys[i];
        float a = src[idx * 3 + 0];
        float c = src[idx * 3 + 1];
        float d = src[idx * 3 + 2];
        out[PAD + i] = make_float4(-2.f * a, -2.f * c, -2.f * d,
                                   fmaf(a, a, fmaf(c, c, d * d)));
    }
}

// ---------------- search: warp-cooperative pruned NN --------------------------
__global__ __launch_bounds__(THREADS)
void chamfer_search_kernel() {
    __shared__ float wsums[NWARP];
    const int dir = blockIdx.z, b = blockIdx.y, chunk = blockIdx.x;
    const float4* __restrict__ rbuf = g_sorted[(dir == 0 ? 1 : 0) * BATCH + b];
    const float4* __restrict__ qbuf = g_sorted[(dir == 0 ? 0 : 1) * BATCH + b];
    const int lane = threadIdx.x & 31, wid = threadIdx.x >> 5;
    const int q0 = chunk * QPB + wid * QPW;

    int p = 0;            // merge pointer: first ref with rz >= qz
    bool first = true;
    float wacc = 0.f;

    for (int qi = 0; qi < QPW; qi++) {
        float4 qv = __ldg(&qbuf[PAD + q0 + qi]);     // broadcast
        float qx = -0.5f * qv.x, qy = -0.5f * qv.y, qz = -0.5f * qv.z;
        float q2 = qv.w;
        float m2qz = qv.z;                           // = -2*qz; "rz<qz" <=> s.z > m2qz

        if (first) {  // coarse advance (stride 128), per warp once
            while (true) {
                int idx = p + lane * 128;
                float sz = __ldg(&rbuf[PAD + (idx < NPTS ? idx : NPTS)]).z;
                int c = __popc(__ballot_sync(0xFFFFFFFFu, sz > m2qz));
                if (c == 0) break;
                p += (c - 1) * 128;
                if (c < 32) break;
            }
            first = false;
        }
        while (true) {  // fine advance (stride 1); pads never satisfy predicate
            float sz = __ldg(&rbuf[PAD + p + lane]).z;
            int c = __popc(__ballot_sync(0xFFFFFFFFu, sz > m2qz));
            p += c;
            if (c < 32) break;
        }
        // p in [0, NPTS]

        // Fixed window [p-256, p+256): branch-free, coalesced, 2 accumulators.
        const int base = p - (WIN / 2);
        float t0 = 1e38f, t1 = 1e38f;
        #pragma unroll
        for (int r = 0; r < WROUNDS; r += 2) {
            float4 f = __ldg(&rbuf[PAD + base + r * 32 + lane]);
            float4 g = __ldg(&rbuf[PAD + base + (r + 1) * 32 + lane]);
            float ta = fmaf(qx, f.x, fmaf(qy, f.y, fmaf(qz, f.z, f.w)));
            float tb = fmaf(qx, g.x, fmaf(qy, g.y, fmaf(qz, g.z, g.w)));
            t0 = fminf(t0, ta);
            t1 = fminf(t1, tb);
        }
        float t = fminf(t0, t1);
        #pragma unroll
        for (int off = 16; off; off >>= 1)
            t = fminf(t, __shfl_xor_sync(0xFFFFFFFFu, t, off));
        float best = q2 + t;   // warp-uniform

        // Sound extension: processed real region [wlo, whi).
        int wlo = base < 0 ? 0 : base;
        int whi = (base + WIN > NPTS) ? NPTS : base + WIN;
        while (true) {
            float gdn = 1e38f, gup = 1e38f;
            if (wlo > 0) {
                float zl = -0.5f * __ldg(&rbuf[PAD + wlo - 1]).z;
                float d = qz - zl; gdn = d * d;
            }
            if (whi < NPTS) {
                float zh = -0.5f * __ldg(&rbuf[PAD + whi]).z;
                float d = zh - qz; gup = d * d;
            }
            if (fminf(gdn, gup) >= best) break;
            int idx;
            if (gdn <= gup) { idx = wlo - 32 + lane; wlo = (wlo >= 32) ? wlo - 32 : 0; }
            else            { idx = whi + lane;      whi = (whi + 32 <= NPTS) ? whi + 32 : NPTS; }
            float4 f = __ldg(&rbuf[PAD + idx]);     // pad reads -> huge dist
            float te = fmaf(qx, f.x, fmaf(qy, f.y, fmaf(qz, f.z, f.w)));
            #pragma unroll
            for (int off = 16; off; off >>= 1)
                te = fminf(te, __shfl_xor_sync(0xFFFFFFFFu, te, off));
            best = fminf(best, q2 + te);
        }

        wacc += best;
    }

    if (lane == 0) wsums[wid] = wacc;
    __syncthreads();
    if (threadIdx.x == 0) {
        float s = 0.f;
        #pragma unroll
        for (int i = 0; i < NWARP; i++) s += wsums[i];
        int bid = (blockIdx.z * BATCH + blockIdx.y) * CHUNKS + blockIdx.x;
        g_bsum[bid] = s;
    }
}

// ---------------- final reduce ------------------------------------------------
__global__ __launch_bounds__(256)
void chamfer_final_kernel(float* __restrict__ out) {
    __shared__ float ws[8];
    float s = 0.f;
    for (int i = threadIdx.x; i < NBLK; i += 256) s += g_bsum[i];
    #pragma unroll
    for (int off = 16; off; off >>= 1)
        s += __shfl_xor_sync(0xFFFFFFFFu, s, off);
    int lane = threadIdx.x & 31, wid = threadIdx.x >> 5;
    if (lane == 0) ws[wid] = s;
    __syncthreads();
    if (threadIdx.x == 0) {
        float v = 0.f;
        #pragma unroll
        for (int i = 0; i < 8; i++) v += ws[i];
        out[0] = v * (1.0f / ((float)BATCH * (float)NPTS));
    }
}

extern "C" void kernel_launch(void* const* d_in, const int* in_sizes, int n_in,
                              void* d_out, int out_size) {
    const float* x = (const float*)d_in[0];
    const float* y = (const float*)d_in[1];
    float* out = (float*)d_out;

    chamfer_sort_kernel<<<dim3(BATCH, 2), STHREADS>>>(x, y);
    chamfer_search_kernel<<<dim3(CHUNKS, BATCH, 2), THREADS>>>();
    chamfer_final_kernel<<<1, 256>>>(out);
}

// round 5
// speedup vs baseline: 1.0646x; 1.0646x over previous
#include <cuda_runtime.h>
#include <cuda_bf16.h>
#include <cstdint>

// ChamferDistance via z-bucketed exact pruned NN search.
// Stage 1: counting-bucketize each (set,batch) by z into 256 uniform buckets,
//          storing transformed points (-2x,-2y,-2z,||p||^2) + bucket starts.
// Stage 2: per-thread NN search over smem-resident bucketed refs, scanning
//          buckets outward from the query's bucket with sound early exit:
//          prune side when (zgap_to_bucket_edge)^2 - q2 >= best_partial.
// Stage 3: tree reduce.

#define BATCH    16
#define NPTS     4096
#define NBUCK    256
#define ZLO      (-4.6f)
#define ZHI      (4.6f)
#define BW       ((ZHI - ZLO) / NBUCK)
#define INVBW    ((float)NBUCK / (ZHI - ZLO))

#define BTHREADS 512
#define STHREADS 512
#define QCHUNK   (NPTS / STHREADS)            // 8 blocks per (dir,b)
#define NSBLK    (QCHUNK * BATCH * 2)         // 256 search blocks
#define FINF     __int_as_float(0x7f800000)

__device__ float4 g_pts[2 * BATCH][NPTS];     // bucketed transformed points
__device__ int    g_start[2 * BATCH][NBUCK + 1];
__device__ float  g_bsum[NSBLK];

__device__ __forceinline__ int bucket_of(float z) {
    int b = (int)floorf((z - ZLO) * INVBW);
    return min(max(b, 0), NBUCK - 1);
}

// ---------------- stage 1: bucketize ----------------------------------------
__global__ __launch_bounds__(BTHREADS)
void chamfer_bucketize_kernel(const float* __restrict__ x,
                              const float* __restrict__ y) {
    __shared__ int cnt[NBUCK];
    __shared__ int start[NBUCK + 1];
    __shared__ int off[NBUCK];
    __shared__ unsigned short bk[NPTS];
    const int b = blockIdx.x, set = blockIdx.y;
    const float* src = (set == 0 ? x : y) + (size_t)b * NPTS * 3;
    const int sb = set * BATCH + b;
    const int tid = threadIdx.x;

    for (int i = tid; i < NBUCK; i += BTHREADS) cnt[i] = 0;
    __syncthreads();
    for (int i = tid; i < NPTS; i += BTHREADS) {
        int bu = bucket_of(src[i * 3 + 2]);
        bk[i] = (unsigned short)bu;
        atomicAdd(&cnt[bu], 1);
    }
    __syncthreads();
    if (tid == 0) {
        int run = 0;
        #pragma unroll 4
        for (int i = 0; i < NBUCK; i++) { start[i] = run; off[i] = run; run += cnt[i]; }
        start[NBUCK] = run;
    }
    __syncthreads();
    for (int i = tid; i <= NBUCK; i += BTHREADS) g_start[sb][i] = start[i];
    for (int i = tid; i < NPTS; i += BTHREADS) {
        int pos = atomicAdd(&off[bk[i]], 1);
        float a = src[i * 3 + 0], c = src[i * 3 + 1], d = src[i * 3 + 2];
        g_pts[sb][pos] = make_float4(-2.f * a, -2.f * c, -2.f * d,
                                     fmaf(a, a, fmaf(c, c, d * d)));
    }
}

// ---------------- stage 2: per-thread pruned search --------------------------
__device__ __forceinline__ void scan_bucket(const float4* __restrict__ refs,
                                            int s, int e,
                                            float qx, float qy, float qz,
                                            float& bestp) {
    int k = s;
    float b0 = bestp, b1 = FINF;
    for (; k + 2 <= e; k += 2) {
        float4 f0 = refs[k];
        float4 f1 = refs[k + 1];
        float d0 = fmaf(qx, f0.x, fmaf(qy, f0.y, fmaf(qz, f0.z, f0.w)));
        float d1 = fmaf(qx, f1.x, fmaf(qy, f1.y, fmaf(qz, f1.z, f1.w)));
        b0 = fminf(b0, d0);
        b1 = fminf(b1, d1);
    }
    if (k < e) {
        float4 f0 = refs[k];
        b0 = fminf(b0, fmaf(qx, f0.x, fmaf(qy, f0.y, fmaf(qz, f0.z, f0.w))));
    }
    bestp = fminf(b0, b1);
}

__global__ __launch_bounds__(STHREADS)
void chamfer_search_kernel() {
    extern __shared__ float4 srefs[];          // NPTS float4 = 64 KB dynamic
    __shared__ int sstart[NBUCK + 1];
    __shared__ float wsum[STHREADS / 32];
    const int chunk = blockIdx.x, b = blockIdx.y, dir = blockIdx.z;
    const int rsb = (dir == 0 ? 1 : 0) * BATCH + b;
    const int qsb = (dir == 0 ? 0 : 1) * BATCH + b;
    const int tid = threadIdx.x;

    for (int i = tid; i < NPTS; i += STHREADS) srefs[i] = g_pts[rsb][i];
    for (int i = tid; i <= NBUCK; i += STHREADS) sstart[i] = g_start[rsb][i];
    __syncthreads();

    const int qi = chunk * STHREADS + tid;
    float4 qv = g_pts[qsb][qi];                // bucketed order: warp-coherent z
    const float qx = -0.5f * qv.x;
    const float qy = -0.5f * qv.y;
    const float qz = -0.5f * qv.z;
    const float q2 = qv.w;

    float bestp = FINF;                        // min over refs of (||r||^2 - 2 q.r)
    const int qb = bucket_of(qz);
    scan_bucket(srefs, sstart[qb], sstart[qb + 1], qx, qy, qz, bestp);

    int bl = qb - 1, bu = qb + 1;
    while (true) {
        float gd2, gu2;
        if (bl >= 0) {
            float g = fmaxf(qz - (ZLO + (float)(bl + 1) * BW), 0.f);
            gd2 = fmaf(g, g, -q2);
        } else gd2 = FINF;
        if (bu < NBUCK) {
            float g = fmaxf((ZLO + (float)bu * BW) - qz, 0.f);
            gu2 = fmaf(g, g, -q2);
        } else gu2 = FINF;
        if (gd2 >= bestp && gu2 >= bestp) break;
        if (gd2 <= gu2) { scan_bucket(srefs, sstart[bl], sstart[bl + 1], qx, qy, qz, bestp); bl--; }
        else            { scan_bucket(srefs, sstart[bu], sstart[bu + 1], qx, qy, qz, bestp); bu++; }
    }

    float val = q2 + bestp;                    // exact NN squared distance

    // Block-sum.
    #pragma unroll
    for (int o = 16; o; o >>= 1) val += __shfl_xor_sync(0xFFFFFFFFu, val, o);
    const int lane = tid & 31, wid = tid >> 5;
    if (lane == 0) wsum[wid] = val;
    __syncthreads();
    if (tid == 0) {
        float s = 0.f;
        #pragma unroll
        for (int i = 0; i < STHREADS / 32; i++) s += wsum[i];
        g_bsum[(blockIdx.z * BATCH + blockIdx.y) * QCHUNK + blockIdx.x] = s;
    }
}

// ---------------- stage 3: final reduce --------------------------------------
__global__ __launch_bounds__(256)
void chamfer_final_kernel(float* __restrict__ out) {
    __shared__ float ws[8];
    float s = (threadIdx.x < NSBLK) ? g_bsum[threadIdx.x] : 0.f;
    #pragma unroll
    for (int o = 16; o; o >>= 1) s += __shfl_xor_sync(0xFFFFFFFFu, s, o);
    int lane = threadIdx.x & 31, wid = threadIdx.x >> 5;
    if (lane == 0) ws[wid] = s;
    __syncthreads();
    if (threadIdx.x == 0) {
        float v = 0.f;
        #pragma unroll
        for (int i = 0; i < 8; i++) v += ws[i];
        out[0] = v * (1.0f / ((float)BATCH * (float)NPTS));
    }
}

extern "C" void kernel_launch(void* const* d_in, const int* in_sizes, int n_in,
                              void* d_out, int out_size) {
    const float* x = (const float*)d_in[0];
    const float* y = (const float*)d_in[1];
    float* out = (float*)d_out;

    cudaFuncSetAttribute(chamfer_search_kernel,
                         cudaFuncAttributeMaxDynamicSharedMemorySize,
                         NPTS * (int)sizeof(float4));

    chamfer_bucketize_kernel<<<dim3(BATCH, 2), BTHREADS>>>(x, y);
    chamfer_search_kernel<<<dim3(QCHUNK, BATCH, 2), STHREADS,
                            NPTS * sizeof(float4)>>>();
    chamfer_final_kernel<<<1, 256>>>(out);
}